// round 8
// baseline (speedup 1.0000x reference)
#include <cuda_runtime.h>
#include <cuda_bf16.h>
#include <cstdint>
#include <cstdio>

// Problem dims (fixed): T=2048, B=8, D=1024
#define TT 2048
#define BB 8
#define DD 1024
#define MROWS (TT*BB)          // 16384

// ---------------------------------------------------------------------------
// Scratch (device globals; no allocation allowed)
// ---------------------------------------------------------------------------
__device__ float g_h   [(size_t)MROWS * DD];          // layernorm(data), tf32-rounded
__device__ float g_qx  [(size_t)MROWS * 5 * DD];      // [q|k|v|x1|gate] projection (N=5120)
__device__ float g_W   [(size_t)TT * TT];             // exp(pos_bias), tf32-rounded
__device__ float g_XT  [(size_t)2 * BB * DD * TT];    // [16384, 2048]: rows 0..8191 ek*v, 8192.. ek
__device__ float g_Y   [(size_t)TT * 2 * BB * DD];    // [2048, 16384]: num | den
__device__ float g_ag  [(size_t)MROWS * 2 * DD];      // [act | gate] per row (K=2048)
__device__ float g_w12 [(size_t)5*DD*DD];             // [qkv_w ; fc1_w] rows, tf32
__device__ float g_w34 [(size_t)DD*2*DD];             // row n = [out_w[n] | fc2_w[n]], tf32
__device__ float g_b12 [(size_t)5*DD];
__device__ float g_b34 [(size_t)DD];

// ---------------------------------------------------------------------------
// Helpers
// ---------------------------------------------------------------------------
__device__ __forceinline__ float to_tf32(float x) {
    float r;
    asm("cvt.rna.tf32.f32 %0, %1;" : "=f"(r) : "f"(x));
    return r;
}
__device__ __forceinline__ void cp_async16(uint32_t saddr, const void* gptr) {
    asm volatile("cp.async.cg.shared.global [%0], [%1], 16;\n" :: "r"(saddr), "l"(gptr));
}
__device__ __forceinline__ void cp_commit() {
    asm volatile("cp.async.commit_group;\n");
}

// ---------------------------------------------------------------------------
// Elementwise / prep kernels
// ---------------------------------------------------------------------------
__global__ void round_tf32_k(const float* __restrict__ src, float* __restrict__ dst, int n) {
    int i = blockIdx.x * blockDim.x + threadIdx.x;
    if (i < n) dst[i] = to_tf32(src[i]);
}

__global__ void prep_w34_k(const float* __restrict__ out_w, const float* __restrict__ fc2_w,
                           float* __restrict__ w34) {
    int i = blockIdx.x * blockDim.x + threadIdx.x;    // < 1024*1024
    int n = i >> 10, c = i & 1023;
    w34[(size_t)n * 2048 + c]        = to_tf32(out_w[i]);
    w34[(size_t)n * 2048 + 1024 + c] = to_tf32(fc2_w[i]);
}

__global__ void prep_bias_k(const float* __restrict__ qkv_b, const float* __restrict__ fc1_b,
                            const float* __restrict__ out_b, const float* __restrict__ fc2_b,
                            float* __restrict__ b12, float* __restrict__ b34) {
    int i = blockIdx.x * blockDim.x + threadIdx.x;    // < 5120
    if (i < 3 * DD) b12[i] = qkv_b[i];
    else            b12[i] = fc1_b[i - 3 * DD];
    if (i < DD)     b34[i] = out_b[i] + fc2_b[i];
}

__global__ void expw_k(const float* __restrict__ pb, float* __restrict__ w, int n) {
    int i = blockIdx.x * blockDim.x + threadIdx.x;
    if (i < n) w[i] = to_tf32(expf(pb[i]));
}

// LayerNorm over last dim (D=1024); one block (256 thr, float4) per row.
__global__ void ln_k(const float* __restrict__ x, float* __restrict__ h) {
    __shared__ float red[16];
    const size_t row = blockIdx.x;
    const float4* xr = (const float4*)(x + row * DD);
    float4 v = xr[threadIdx.x];
    float s = v.x + v.y + v.z + v.w;
    float q = v.x*v.x + v.y*v.y + v.z*v.z + v.w*v.w;
    #pragma unroll
    for (int o = 16; o; o >>= 1) {
        s += __shfl_xor_sync(0xffffffffu, s, o);
        q += __shfl_xor_sync(0xffffffffu, q, o);
    }
    int wid = threadIdx.x >> 5;
    if ((threadIdx.x & 31) == 0) { red[wid] = s; red[8 + wid] = q; }
    __syncthreads();
    s = 0.f; q = 0.f;
    #pragma unroll
    for (int i = 0; i < 8; i++) { s += red[i]; q += red[8 + i]; }
    float mean = s * (1.0f / DD);
    float var  = fmaxf(q * (1.0f / DD) - mean * mean, 0.0f);
    float rs   = rsqrtf(var + 1.17549435e-38f);
    float4 o;
    o.x = to_tf32((v.x - mean) * rs);
    o.y = to_tf32((v.y - mean) * rs);
    o.z = to_tf32((v.z - mean) * rs);
    o.w = to_tf32((v.w - mean) * rs);
    ((float4*)(h + row * DD))[threadIdx.x] = o;
}

// Build XT[n, j]: n = b*D+d (rows 0..8191: ek*v, 8192..: ek), j = time index.
__global__ void make_xt_k(const float* __restrict__ qx, float* __restrict__ XT) {
    __shared__ float s_ekv[32][33];
    __shared__ float s_ek [32][33];
    const int d0 = blockIdx.x * 32;
    const int j0 = blockIdx.y * 32;
    const int b  = blockIdx.z;
    const int x  = threadIdx.x;
    #pragma unroll
    for (int i = 0; i < 4; i++) {
        int j = threadIdx.y + i * 8;
        const float* row = qx + ((size_t)(j0 + j) * BB + b) * (5 * DD);
        float kk = row[DD + d0 + x];
        float vv = row[2 * DD + d0 + x];
        float ek = expf(kk);
        s_ek[j][x]  = ek;
        s_ekv[j][x] = ek * vv;
    }
    __syncthreads();
    #pragma unroll
    for (int i = 0; i < 4; i++) {
        int d = threadIdx.y + i * 8;
        size_t n = (size_t)b * DD + d0 + d;
        XT[n * TT + j0 + x]                     = to_tf32(s_ekv[x][d]);
        XT[(n + (size_t)BB * DD) * TT + j0 + x] = to_tf32(s_ek[x][d]);
    }
}

// ag[:, 0:1024] = tf32( sigmoid(q) * num/den )
__global__ void act_k(const float* __restrict__ qx, const float* __restrict__ Y,
                      float* __restrict__ ag) {
    size_t idx = (size_t)blockIdx.x * blockDim.x + threadIdx.x;
    int m = (int)(idx >> 10);
    int d = (int)(idx & 1023);
    int t = m >> 3;
    int b = m & 7;
    float q = qx[(size_t)m * (5 * DD) + d];
    size_t yb = (size_t)t * (2 * BB * DD) + (size_t)b * DD + d;
    float num = Y[yb];
    float den = Y[yb + (size_t)BB * DD];
    float sg = 1.0f / (1.0f + expf(-q));
    ag[(size_t)m * (2 * DD) + d] = to_tf32(sg * (num / den));
}

// ag[:, 1024:2048] = tf32( x1 * mish(gate) ), mish(x) = x*tanh(softplus(x))
__global__ void swiglu_k(const float* __restrict__ qx, float* __restrict__ ag) {
    size_t idx = (size_t)blockIdx.x * blockDim.x + threadIdx.x;
    int m = (int)(idx >> 10);
    int d = (int)(idx & 1023);
    const float* r = qx + (size_t)m * (5 * DD);
    float x1 = r[3 * DD + d];
    float gt = r[4 * DD + d];
    float sp = (gt > 20.0f) ? gt : log1pf(expf(gt));
    ag[(size_t)m * (2 * DD) + DD + d] = to_tf32(x1 * gt * tanhf(sp));
}

// ---------------------------------------------------------------------------
// GEMM (TN): C[M,N] = A[M,K] * B[N,K]^T  (+ bias[n]) (+ aux[m,n])
// tf32 mma.sync m16n8k8, 128x128x32 block tile, 8 warps (64x32 warp tiles),
// cp.async 3-stage smem pipeline, stride-36 padding.
// ---------------------------------------------------------------------------
#define BM 128
#define BN 128
#define BK 32
#define STR 36
#define STAGES 3
#define TILE_F (BM * STR)                       // floats per matrix per stage
#define STAGE_F (2 * TILE_F)                    // A + B per stage
#define SMEM_BYTES (STAGES * STAGE_F * 4)       // 110,592 B

template<bool HAS_BIAS, bool HAS_AUX>
__global__ void __launch_bounds__(256) gemm_tn(
    const float* __restrict__ A, const float* __restrict__ B,
    const float* __restrict__ bias, const float* __restrict__ aux,
    float* __restrict__ C, int M, int N, int K)
{
    extern __shared__ float sm[];

    const int tid = threadIdx.x;
    const size_t m0 = (size_t)blockIdx.y * BM;
    const size_t n0 = (size_t)blockIdx.x * BN;

    // global->smem load mapping: per matrix 1024 float4, 4 per thread
    const int lr = tid >> 3;   // 0..31 (row, +32*i)
    const int lc = tid & 7;    // float4 column
    const float* gA = A + (m0 + lr) * (size_t)K + lc * 4;
    const float* gB = B + (n0 + lr) * (size_t)K + lc * 4;
    const uint32_t sAa = (uint32_t)__cvta_generic_to_shared(&sm[lr * STR + lc * 4]);
    const uint32_t sBa = sAa + TILE_F * 4;

    const int warp = tid >> 5, lane = tid & 31;
    const int g = lane >> 2, tg = lane & 3;
    const int wm = (warp >> 2) * 64;   // 0 or 64
    const int wn = (warp & 3) * 32;    // 0,32,64,96

    float c[4][4][4];
    #pragma unroll
    for (int i = 0; i < 4; i++)
        #pragma unroll
        for (int j = 0; j < 4; j++)
            #pragma unroll
            for (int e = 0; e < 4; e++) c[i][j][e] = 0.0f;

    const int nk = K / BK;

    // prologue: prefetch stages 0 and 1
    #pragma unroll
    for (int st = 0; st < 2; st++) {
        const uint32_t da = sAa + st * STAGE_F * 4;
        const uint32_t db = sBa + st * STAGE_F * 4;
        const size_t ko = (size_t)st * BK;
        #pragma unroll
        for (int i = 0; i < 4; i++) {
            cp_async16(da + i * 32 * STR * 4, gA + ko + (size_t)(32 * i) * K);
            cp_async16(db + i * 32 * STR * 4, gB + ko + (size_t)(32 * i) * K);
        }
        cp_commit();
    }

    int slot = 0;       // slot of tile kt
    int wslot = 2;      // slot to write tile kt+2
    for (int kt = 0; kt < nk; kt++) {
        if (kt < nk - 1) asm volatile("cp.async.wait_group 1;\n" ::: "memory");
        else             asm volatile("cp.async.wait_group 0;\n" ::: "memory");
        __syncthreads();

        if (kt + 2 < nk) {
            const uint32_t da = sAa + wslot * STAGE_F * 4;
            const uint32_t db = sBa + wslot * STAGE_F * 4;
            const size_t ko = (size_t)(kt + 2) * BK;
            #pragma unroll
            for (int i = 0; i < 4; i++) {
                cp_async16(da + i * 32 * STR * 4, gA + ko + (size_t)(32 * i) * K);
                cp_async16(db + i * 32 * STR * 4, gB + ko + (size_t)(32 * i) * K);
            }
            cp_commit();
        }

        const float* Ab = sm + slot * STAGE_F;
        const float* Bb = Ab + TILE_F;
        #pragma unroll
        for (int ks = 0; ks < 4; ks++) {
            const int k = ks * 8;
            uint32_t af[4][4], bf[4][2];
            #pragma unroll
            for (int mt = 0; mt < 4; mt++) {
                const uint32_t* p = (const uint32_t*)(Ab + (wm + mt * 16 + g) * STR + k + tg);
                af[mt][0] = p[0];
                af[mt][1] = p[8 * STR];
                af[mt][2] = p[4];
                af[mt][3] = p[8 * STR + 4];
            }
            #pragma unroll
            for (int nt = 0; nt < 4; nt++) {
                const uint32_t* p = (const uint32_t*)(Bb + (wn + nt * 8 + g) * STR + k + tg);
                bf[nt][0] = p[0];
                bf[nt][1] = p[4];
            }
            #pragma unroll
            for (int mt = 0; mt < 4; mt++)
                #pragma unroll
                for (int nt = 0; nt < 4; nt++) {
                    asm volatile(
                        "mma.sync.aligned.m16n8k8.row.col.f32.tf32.tf32.f32 "
                        "{%0,%1,%2,%3}, {%4,%5,%6,%7}, {%8,%9}, {%0,%1,%2,%3};\n"
                        : "+f"(c[mt][nt][0]), "+f"(c[mt][nt][1]),
                          "+f"(c[mt][nt][2]), "+f"(c[mt][nt][3])
                        : "r"(af[mt][0]), "r"(af[mt][1]), "r"(af[mt][2]), "r"(af[mt][3]),
                          "r"(bf[nt][0]), "r"(bf[nt][1]));
                }
        }
        slot  = (slot  == STAGES - 1) ? 0 : slot + 1;
        wslot = (wslot == STAGES - 1) ? 0 : wslot + 1;
    }

    // epilogue: direct stores (regs -> gmem), fused bias / residual
    #pragma unroll
    for (int mt = 0; mt < 4; mt++) {
        const size_t r0 = m0 + wm + mt * 16 + g;
        const size_t r1 = r0 + 8;
        #pragma unroll
        for (int nt = 0; nt < 4; nt++) {
            const size_t col = n0 + wn + nt * 8 + tg * 2;
            float b0 = 0.f, b1 = 0.f;
            if (HAS_BIAS) { b0 = bias[col]; b1 = bias[col + 1]; }
            const size_t i0 = r0 * N + col;
            const size_t i1 = r1 * N + col;
            float v0 = c[mt][nt][0] + b0;
            float v1 = c[mt][nt][1] + b1;
            float v2 = c[mt][nt][2] + b0;
            float v3 = c[mt][nt][3] + b1;
            if (HAS_AUX) {
                v0 += aux[i0]; v1 += aux[i0 + 1];
                v2 += aux[i1]; v3 += aux[i1 + 1];
            }
            C[i0] = v0; C[i0 + 1] = v1;
            C[i1] = v2; C[i1 + 1] = v3;
        }
    }
}

// ---------------------------------------------------------------------------
// Host launch
// ---------------------------------------------------------------------------
extern "C" void kernel_launch(void* const* d_in, const int* in_sizes, int n_in,
                              void* d_out, int out_size) {
    const float* data  = (const float*)d_in[0];
    const float* qkv_w = (const float*)d_in[1];
    const float* qkv_b = (const float*)d_in[2];
    const float* pos_b = (const float*)d_in[3];
    const float* out_w = (const float*)d_in[4];
    const float* out_b = (const float*)d_in[5];
    const float* fc1_w = (const float*)d_in[6];
    const float* fc1_b = (const float*)d_in[7];
    const float* fc2_w = (const float*)d_in[8];
    const float* fc2_b = (const float*)d_in[9];
    float* out = (float*)d_out;

    float *h, *qx, *W, *XT, *Y, *ag, *w12, *w34, *b12, *b34;
    cudaGetSymbolAddress((void**)&h,   g_h);
    cudaGetSymbolAddress((void**)&qx,  g_qx);
    cudaGetSymbolAddress((void**)&W,   g_W);
    cudaGetSymbolAddress((void**)&XT,  g_XT);
    cudaGetSymbolAddress((void**)&Y,   g_Y);
    cudaGetSymbolAddress((void**)&ag,  g_ag);
    cudaGetSymbolAddress((void**)&w12, g_w12);
    cudaGetSymbolAddress((void**)&w34, g_w34);
    cudaGetSymbolAddress((void**)&b12, g_b12);
    cudaGetSymbolAddress((void**)&b34, g_b34);

    cudaFuncSetAttribute(gemm_tn<true,  false>, cudaFuncAttributeMaxDynamicSharedMemorySize, SMEM_BYTES);
    cudaFuncSetAttribute(gemm_tn<false, false>, cudaFuncAttributeMaxDynamicSharedMemorySize, SMEM_BYTES);
    cudaFuncSetAttribute(gemm_tn<true,  true >, cudaFuncAttributeMaxDynamicSharedMemorySize, SMEM_BYTES);

    // weight / bias prep
    round_tf32_k<<<(3*DD*DD + 255)/256, 256>>>(qkv_w, w12, 3*DD*DD);
    round_tf32_k<<<(2*DD*DD + 255)/256, 256>>>(fc1_w, w12 + (size_t)3*DD*DD, 2*DD*DD);
    prep_w34_k<<<(DD*DD + 255)/256, 256>>>(out_w, fc2_w, w34);
    prep_bias_k<<<(5*DD + 255)/256, 256>>>(qkv_b, fc1_b, out_b, fc2_b, b12, b34);

    // layernorm + exp(pos_bias)
    ln_k<<<MROWS, 256>>>(data, h);
    expw_k<<<(TT*TT + 255)/256, 256>>>(pos_b, W, TT*TT);

    // qx = h @ w12^T + b12    [16384, 5120]  (fused qkv + fc1)
    gemm_tn<true, false><<<dim3(5*DD/BN, MROWS/BM), 256, SMEM_BYTES>>>(
        h, w12, b12, nullptr, qx, MROWS, 5*DD, DD);

    // gate half of ag (independent of attention path)
    swiglu_k<<<(MROWS*DD)/256, 256>>>(qx, ag);

    // XT = [ek*v ; ek] transposed to [16384, 2048]
    make_xt_k<<<dim3(DD/32, TT/32, BB), dim3(32, 8)>>>(qx, XT);

    // Y = W @ XT^T  -> [2048, 16384]
    gemm_tn<false, false><<<dim3(2*BB*DD/BN, TT/BM), 256, SMEM_BYTES>>>(
        W, XT, nullptr, nullptr, Y, TT, 2*BB*DD, TT);

    // act half of ag
    act_k<<<(MROWS*DD)/256, 256>>>(qx, Y, ag);

    // out = data + ag @ w34^T + b34   (fused out-proj + fc2)
    gemm_tn<true, true><<<dim3(DD/BN, MROWS/BM), 256, SMEM_BYTES>>>(
        ag, w34, b34, data, out, MROWS, DD, 2*DD);
}

// round 9
// speedup vs baseline: 1.6406x; 1.6406x over previous
#include <cuda_runtime.h>
#include <cuda_fp16.h>
#include <cstdint>
#include <cstdio>

// Problem dims (fixed): T=2048, B=8, D=1024
#define TT 2048
#define BB 8
#define DD 1024
#define MROWS (TT*BB)          // 16384

// ---------------------------------------------------------------------------
// Scratch (device globals; no allocation allowed)
// ---------------------------------------------------------------------------
__device__ __half g_h  [(size_t)MROWS * DD];          // layernorm(data), fp16
__device__ float  g_qx [(size_t)MROWS * 5 * DD];      // [q|k|v|x1|gate] projection (N=5120)
__device__ __half g_W  [(size_t)TT * TT];             // exp(pos_bias), fp16
__device__ __half g_XT [(size_t)2 * BB * DD * TT];    // [16384, 2048]: rows 0..8191 ek*v, 8192.. ek
__device__ float  g_Y  [(size_t)TT * 2 * BB * DD];    // [2048, 16384]: num | den
__device__ __half g_ag [(size_t)MROWS * 2 * DD];      // [act | gate] per row (K=2048)
__device__ __half g_w12[(size_t)5*DD*DD];             // [qkv_w ; fc1_w] rows, fp16
__device__ __half g_w34[(size_t)DD*2*DD];             // row n = [out_w[n] | fc2_w[n]], fp16
__device__ float  g_b12[(size_t)5*DD];
__device__ float  g_b34[(size_t)DD];

// ---------------------------------------------------------------------------
// Helpers
// ---------------------------------------------------------------------------
__device__ __forceinline__ void cp_async16(uint32_t saddr, const void* gptr) {
    asm volatile("cp.async.cg.shared.global [%0], [%1], 16;\n" :: "r"(saddr), "l"(gptr));
}
__device__ __forceinline__ void cp_commit() {
    asm volatile("cp.async.commit_group;\n");
}

// ---------------------------------------------------------------------------
// Elementwise / prep kernels
// ---------------------------------------------------------------------------
__global__ void conv_half_k(const float* __restrict__ src, __half* __restrict__ dst, int n) {
    int i = blockIdx.x * blockDim.x + threadIdx.x;
    if (i < n) dst[i] = __float2half_rn(src[i]);
}

__global__ void prep_w34_k(const float* __restrict__ out_w, const float* __restrict__ fc2_w,
                           __half* __restrict__ w34) {
    int i = blockIdx.x * blockDim.x + threadIdx.x;    // < 1024*1024
    int n = i >> 10, c = i & 1023;
    w34[(size_t)n * 2048 + c]        = __float2half_rn(out_w[i]);
    w34[(size_t)n * 2048 + 1024 + c] = __float2half_rn(fc2_w[i]);
}

__global__ void prep_bias_k(const float* __restrict__ qkv_b, const float* __restrict__ fc1_b,
                            const float* __restrict__ out_b, const float* __restrict__ fc2_b,
                            float* __restrict__ b12, float* __restrict__ b34) {
    int i = blockIdx.x * blockDim.x + threadIdx.x;    // < 5120
    if (i < 3 * DD) b12[i] = qkv_b[i];
    else            b12[i] = fc1_b[i - 3 * DD];
    if (i < DD)     b34[i] = out_b[i] + fc2_b[i];
}

__global__ void expw_k(const float* __restrict__ pb, __half* __restrict__ w, int n) {
    int i = blockIdx.x * blockDim.x + threadIdx.x;
    if (i < n) w[i] = __float2half_rn(expf(pb[i]));
}

// LayerNorm over last dim (D=1024); one block (256 thr, float4) per row.
__global__ void ln_k(const float* __restrict__ x, __half* __restrict__ h) {
    __shared__ float red[16];
    const size_t row = blockIdx.x;
    const float4* xr = (const float4*)(x + row * DD);
    float4 v = xr[threadIdx.x];
    float s = v.x + v.y + v.z + v.w;
    float q = v.x*v.x + v.y*v.y + v.z*v.z + v.w*v.w;
    #pragma unroll
    for (int o = 16; o; o >>= 1) {
        s += __shfl_xor_sync(0xffffffffu, s, o);
        q += __shfl_xor_sync(0xffffffffu, q, o);
    }
    int wid = threadIdx.x >> 5;
    if ((threadIdx.x & 31) == 0) { red[wid] = s; red[8 + wid] = q; }
    __syncthreads();
    s = 0.f; q = 0.f;
    #pragma unroll
    for (int i = 0; i < 8; i++) { s += red[i]; q += red[8 + i]; }
    float mean = s * (1.0f / DD);
    float var  = fmaxf(q * (1.0f / DD) - mean * mean, 0.0f);
    float rs   = rsqrtf(var + 1.17549435e-38f);
    __half2* hr = (__half2*)(h + row * DD);
    hr[2*threadIdx.x]     = __floats2half2_rn((v.x - mean) * rs, (v.y - mean) * rs);
    hr[2*threadIdx.x + 1] = __floats2half2_rn((v.z - mean) * rs, (v.w - mean) * rs);
}

// Build XT[n, j]: n = b*D+d (rows 0..8191: ek*v, 8192..: ek), j = time index.
__global__ void make_xt_k(const float* __restrict__ qx, __half* __restrict__ XT) {
    __shared__ float s_ekv[32][33];
    __shared__ float s_ek [32][33];
    const int d0 = blockIdx.x * 32;
    const int j0 = blockIdx.y * 32;
    const int b  = blockIdx.z;
    const int x  = threadIdx.x;
    #pragma unroll
    for (int i = 0; i < 4; i++) {
        int j = threadIdx.y + i * 8;
        const float* row = qx + ((size_t)(j0 + j) * BB + b) * (5 * DD);
        float kk = row[DD + d0 + x];
        float vv = row[2 * DD + d0 + x];
        float ek = expf(kk);
        s_ek[j][x]  = ek;
        s_ekv[j][x] = ek * vv;
    }
    __syncthreads();
    #pragma unroll
    for (int i = 0; i < 4; i++) {
        int d = threadIdx.y + i * 8;
        size_t n = (size_t)b * DD + d0 + d;
        XT[n * TT + j0 + x]                     = __float2half_rn(s_ekv[x][d]);
        XT[(n + (size_t)BB * DD) * TT + j0 + x] = __float2half_rn(s_ek[x][d]);
    }
}

// ag[:, 0:1024] = fp16( sigmoid(q) * num/den )
__global__ void act_k(const float* __restrict__ qx, const float* __restrict__ Y,
                      __half* __restrict__ ag) {
    size_t idx = (size_t)blockIdx.x * blockDim.x + threadIdx.x;
    int m = (int)(idx >> 10);
    int d = (int)(idx & 1023);
    int t = m >> 3;
    int b = m & 7;
    float q = qx[(size_t)m * (5 * DD) + d];
    size_t yb = (size_t)t * (2 * BB * DD) + (size_t)b * DD + d;
    float num = Y[yb];
    float den = Y[yb + (size_t)BB * DD];
    float sg = 1.0f / (1.0f + expf(-q));
    ag[(size_t)m * (2 * DD) + d] = __float2half_rn(sg * (num / den));
}

// ag[:, 1024:2048] = fp16( x1 * mish(gate) ), mish(x) = x*tanh(softplus(x))
__global__ void swiglu_k(const float* __restrict__ qx, __half* __restrict__ ag) {
    size_t idx = (size_t)blockIdx.x * blockDim.x + threadIdx.x;
    int m = (int)(idx >> 10);
    int d = (int)(idx & 1023);
    const float* r = qx + (size_t)m * (5 * DD);
    float x1 = r[3 * DD + d];
    float gt = r[4 * DD + d];
    float sp = (gt > 20.0f) ? gt : log1pf(expf(gt));
    ag[(size_t)m * (2 * DD) + DD + d] = __float2half_rn(x1 * gt * tanhf(sp));
}

// ---------------------------------------------------------------------------
// GEMM (TN): C[M,N] = A[M,K] * B[N,K]^T  (+ bias[n]) (+ aux[m,n])
// fp16 mma.sync m16n8k16 (fp32 accum), 128x128x32 block tile, 8 warps,
// cp.async 4-stage smem pipeline, 40-half row padding (conflict-free LDS).
// ---------------------------------------------------------------------------
#define BM 128
#define BN 128
#define BK 32                                   // halves per k-tile
#define STRH 40                                 // halves per smem row (pad 32->40)
#define STAGES 4
#define TILE_H (BM * STRH)                      // halves per matrix per stage (5120)
#define STAGE_H (2 * TILE_H)                    // A + B per stage
#define SMEM_BYTES (STAGES * STAGE_H * 2)       // 81,920 B

template<bool HAS_BIAS, bool HAS_AUX>
__global__ void __launch_bounds__(256) gemm_tn(
    const __half* __restrict__ A, const __half* __restrict__ B,
    const float* __restrict__ bias, const float* __restrict__ aux,
    float* __restrict__ C, int M, int N, int K)
{
    extern __shared__ __half sm[];

    const int tid = threadIdx.x;
    const size_t m0 = (size_t)blockIdx.y * BM;
    const size_t n0 = (size_t)blockIdx.x * BN;

    // global->smem: per matrix per stage 128 rows x 4 chunks(16B=8 halves),
    // 512 chunks, 256 threads -> 2 chunks each.
    const int lr = tid >> 2;          // 0..63 (row, +64*i)
    const int lc = tid & 3;           // 16B chunk within row
    const __half* gA = A + (m0 + lr) * (size_t)K + lc * 8;
    const __half* gB = B + (n0 + lr) * (size_t)K + lc * 8;
    const uint32_t sAa = (uint32_t)__cvta_generic_to_shared(&sm[lr * STRH + lc * 8]);
    const uint32_t sBa = sAa + TILE_H * 2;

    const int warp = tid >> 5, lane = tid & 31;
    const int g = lane >> 2, tg = lane & 3;
    const int wm = (warp >> 2) * 64;   // 0 or 64
    const int wn = (warp & 3) * 32;    // 0,32,64,96

    float c[4][4][4];
    #pragma unroll
    for (int i = 0; i < 4; i++)
        #pragma unroll
        for (int j = 0; j < 4; j++)
            #pragma unroll
            for (int e = 0; e < 4; e++) c[i][j][e] = 0.0f;

    const int nk = K / BK;

    // prologue: prefetch stages 0..2
    #pragma unroll
    for (int st = 0; st < STAGES - 1; st++) {
        const uint32_t da = sAa + st * STAGE_H * 2;
        const uint32_t db = sBa + st * STAGE_H * 2;
        const size_t ko = (size_t)st * BK;
        #pragma unroll
        for (int i = 0; i < 2; i++) {
            cp_async16(da + i * 64 * STRH * 2, gA + ko + (size_t)(64 * i) * K);
            cp_async16(db + i * 64 * STRH * 2, gB + ko + (size_t)(64 * i) * K);
        }
        cp_commit();
    }

    int slot = 0;
    int wslot = STAGES - 1;
    for (int kt = 0; kt < nk; kt++) {
        asm volatile("cp.async.wait_group %0;\n" :: "n"(STAGES - 2) : "memory");
        __syncthreads();

        if (kt + STAGES - 1 < nk) {
            const uint32_t da = sAa + wslot * STAGE_H * 2;
            const uint32_t db = sBa + wslot * STAGE_H * 2;
            const size_t ko = (size_t)(kt + STAGES - 1) * BK;
            #pragma unroll
            for (int i = 0; i < 2; i++) {
                cp_async16(da + i * 64 * STRH * 2, gA + ko + (size_t)(64 * i) * K);
                cp_async16(db + i * 64 * STRH * 2, gB + ko + (size_t)(64 * i) * K);
            }
        }
        cp_commit();   // empty group near tail keeps wait_group accounting valid

        const __half* Ab = sm + slot * STAGE_H;
        const __half* Bb = Ab + TILE_H;
        #pragma unroll
        for (int ks = 0; ks < 2; ks++) {           // two k16 steps per 32-half tile
            const int kh = ks * 16 + 2 * tg;
            uint32_t af[4][4], bf[4][2];
            #pragma unroll
            for (int mt = 0; mt < 4; mt++) {
                const uint32_t* p = (const uint32_t*)(Ab + (wm + mt * 16 + g) * STRH + kh);
                af[mt][0] = p[0];          // row g,    k 2t..2t+1
                af[mt][1] = p[160];        // row g+8 (+8*40 halves = +160 u32)
                af[mt][2] = p[4];          // row g,    k 2t+8..
                af[mt][3] = p[164];        // row g+8,  k 2t+8..
            }
            #pragma unroll
            for (int nt = 0; nt < 4; nt++) {
                const uint32_t* p = (const uint32_t*)(Bb + (wn + nt * 8 + g) * STRH + kh);
                bf[nt][0] = p[0];
                bf[nt][1] = p[4];
            }
            #pragma unroll
            for (int mt = 0; mt < 4; mt++)
                #pragma unroll
                for (int nt = 0; nt < 4; nt++) {
                    asm volatile(
                        "mma.sync.aligned.m16n8k16.row.col.f32.f16.f16.f32 "
                        "{%0,%1,%2,%3}, {%4,%5,%6,%7}, {%8,%9}, {%0,%1,%2,%3};\n"
                        : "+f"(c[mt][nt][0]), "+f"(c[mt][nt][1]),
                          "+f"(c[mt][nt][2]), "+f"(c[mt][nt][3])
                        : "r"(af[mt][0]), "r"(af[mt][1]), "r"(af[mt][2]), "r"(af[mt][3]),
                          "r"(bf[nt][0]), "r"(bf[nt][1]));
                }
        }
        slot  = (slot  == STAGES - 1) ? 0 : slot + 1;
        wslot = (wslot == STAGES - 1) ? 0 : wslot + 1;
    }

    // epilogue: direct stores (regs -> gmem), fused bias / residual
    #pragma unroll
    for (int mt = 0; mt < 4; mt++) {
        const size_t r0 = m0 + wm + mt * 16 + g;
        const size_t r1 = r0 + 8;
        #pragma unroll
        for (int nt = 0; nt < 4; nt++) {
            const size_t col = n0 + wn + nt * 8 + tg * 2;
            float b0 = 0.f, b1 = 0.f;
            if (HAS_BIAS) { b0 = bias[col]; b1 = bias[col + 1]; }
            const size_t i0 = r0 * N + col;
            const size_t i1 = r1 * N + col;
            float v0 = c[mt][nt][0] + b0;
            float v1 = c[mt][nt][1] + b1;
            float v2 = c[mt][nt][2] + b0;
            float v3 = c[mt][nt][3] + b1;
            if (HAS_AUX) {
                v0 += aux[i0]; v1 += aux[i0 + 1];
                v2 += aux[i1]; v3 += aux[i1 + 1];
            }
            C[i0] = v0; C[i0 + 1] = v1;
            C[i1] = v2; C[i1 + 1] = v3;
        }
    }
}

// ---------------------------------------------------------------------------
// Host launch
// ---------------------------------------------------------------------------
extern "C" void kernel_launch(void* const* d_in, const int* in_sizes, int n_in,
                              void* d_out, int out_size) {
    const float* data  = (const float*)d_in[0];
    const float* qkv_w = (const float*)d_in[1];
    const float* qkv_b = (const float*)d_in[2];
    const float* pos_b = (const float*)d_in[3];
    const float* out_w = (const float*)d_in[4];
    const float* out_b = (const float*)d_in[5];
    const float* fc1_w = (const float*)d_in[6];
    const float* fc1_b = (const float*)d_in[7];
    const float* fc2_w = (const float*)d_in[8];
    const float* fc2_b = (const float*)d_in[9];
    float* out = (float*)d_out;

    __half *h, *W, *XT, *ag, *w12, *w34;
    float *qx, *Y, *b12, *b34;
    cudaGetSymbolAddress((void**)&h,   g_h);
    cudaGetSymbolAddress((void**)&qx,  g_qx);
    cudaGetSymbolAddress((void**)&W,   g_W);
    cudaGetSymbolAddress((void**)&XT,  g_XT);
    cudaGetSymbolAddress((void**)&Y,   g_Y);
    cudaGetSymbolAddress((void**)&ag,  g_ag);
    cudaGetSymbolAddress((void**)&w12, g_w12);
    cudaGetSymbolAddress((void**)&w34, g_w34);
    cudaGetSymbolAddress((void**)&b12, g_b12);
    cudaGetSymbolAddress((void**)&b34, g_b34);

    cudaFuncSetAttribute(gemm_tn<true,  false>, cudaFuncAttributeMaxDynamicSharedMemorySize, SMEM_BYTES);
    cudaFuncSetAttribute(gemm_tn<false, false>, cudaFuncAttributeMaxDynamicSharedMemorySize, SMEM_BYTES);
    cudaFuncSetAttribute(gemm_tn<true,  true >, cudaFuncAttributeMaxDynamicSharedMemorySize, SMEM_BYTES);

    // weight / bias prep
    conv_half_k<<<(3*DD*DD + 255)/256, 256>>>(qkv_w, w12, 3*DD*DD);
    conv_half_k<<<(2*DD*DD + 255)/256, 256>>>(fc1_w, w12 + (size_t)3*DD*DD, 2*DD*DD);
    prep_w34_k<<<(DD*DD + 255)/256, 256>>>(out_w, fc2_w, w34);
    prep_bias_k<<<(5*DD + 255)/256, 256>>>(qkv_b, fc1_b, out_b, fc2_b, b12, b34);

    // layernorm + exp(pos_bias)
    ln_k<<<MROWS, 256>>>(data, h);
    expw_k<<<(TT*TT + 255)/256, 256>>>(pos_b, W, TT*TT);

    // qx = h @ w12^T + b12    [16384, 5120]  (fused qkv + fc1)
    gemm_tn<true, false><<<dim3(5*DD/BN, MROWS/BM), 256, SMEM_BYTES>>>(
        h, w12, b12, nullptr, qx, MROWS, 5*DD, DD);

    // gate half of ag (independent of attention path)
    swiglu_k<<<(MROWS*DD)/256, 256>>>(qx, ag);

    // XT = [ek*v ; ek] transposed to [16384, 2048]
    make_xt_k<<<dim3(DD/32, TT/32, BB), dim3(32, 8)>>>(qx, XT);

    // Y = W @ XT^T  -> [2048, 16384]
    gemm_tn<false, false><<<dim3(2*BB*DD/BN, TT/BM), 256, SMEM_BYTES>>>(
        W, XT, nullptr, nullptr, Y, TT, 2*BB*DD, TT);

    // act half of ag
    act_k<<<(MROWS*DD)/256, 256>>>(qx, Y, ag);

    // out = data + ag @ w34^T + b34   (fused out-proj + fc2)
    gemm_tn<true, true><<<dim3(DD/BN, MROWS/BM), 256, SMEM_BYTES>>>(
        ag, w34, b34, data, out, MROWS, DD, 2*DD);
}

// round 10
// speedup vs baseline: 1.8065x; 1.1011x over previous
#include <cuda_runtime.h>
#include <cuda_fp16.h>
#include <cstdint>
#include <cstdio>

// Problem dims (fixed): T=2048, B=8, D=1024
#define TT 2048
#define BB 8
#define DD 1024
#define MROWS (TT*BB)          // 16384

// ---------------------------------------------------------------------------
// Scratch (device globals; no allocation allowed)
// ---------------------------------------------------------------------------
__device__ __half g_h  [(size_t)MROWS * DD];          // layernorm(data), fp16
__device__ __half g_qx [(size_t)MROWS * 5 * DD];      // [q|k|v|x1|gate], fp16
__device__ __half g_W  [(size_t)TT * TT];             // exp(pos_bias), fp16
__device__ __half g_XT [(size_t)2 * BB * DD * TT];    // [16384, 2048]: row 2n = ek*v, 2n+1 = ek (n=b*D+d)
__device__ __half g_ag [(size_t)MROWS * 2 * DD];      // [act | gate] per row (K=2048)
__device__ __half g_w12[(size_t)5*DD*DD];             // [qkv_w ; fc1_w] rows, fp16
__device__ __half g_w34[(size_t)DD*2*DD];             // row n = [out_w[n] | fc2_w[n]], fp16
__device__ float  g_b12[(size_t)5*DD];
__device__ float  g_b34[(size_t)DD];

// ---------------------------------------------------------------------------
// Helpers
// ---------------------------------------------------------------------------
__device__ __forceinline__ void cp_async16(uint32_t saddr, const void* gptr) {
    asm volatile("cp.async.cg.shared.global [%0], [%1], 16;\n" :: "r"(saddr), "l"(gptr));
}
__device__ __forceinline__ void cp_commit() {
    asm volatile("cp.async.commit_group;\n");
}
__device__ __forceinline__ void ldsm_x4(uint32_t& r0, uint32_t& r1, uint32_t& r2, uint32_t& r3,
                                        uint32_t addr) {
    asm volatile("ldmatrix.sync.aligned.m8n8.x4.shared.b16 {%0,%1,%2,%3}, [%4];"
                 : "=r"(r0), "=r"(r1), "=r"(r2), "=r"(r3) : "r"(addr));
}

// ---------------------------------------------------------------------------
// Elementwise / prep kernels
// ---------------------------------------------------------------------------
__global__ void conv_half_k(const float* __restrict__ src, __half* __restrict__ dst, int n) {
    int i = blockIdx.x * blockDim.x + threadIdx.x;
    if (i < n) dst[i] = __float2half_rn(src[i]);
}

__global__ void prep_w34_k(const float* __restrict__ out_w, const float* __restrict__ fc2_w,
                           __half* __restrict__ w34) {
    int i = blockIdx.x * blockDim.x + threadIdx.x;    // < 1024*1024
    int n = i >> 10, c = i & 1023;
    w34[(size_t)n * 2048 + c]        = __float2half_rn(out_w[i]);
    w34[(size_t)n * 2048 + 1024 + c] = __float2half_rn(fc2_w[i]);
}

__global__ void prep_bias_k(const float* __restrict__ qkv_b, const float* __restrict__ fc1_b,
                            const float* __restrict__ out_b, const float* __restrict__ fc2_b,
                            float* __restrict__ b12, float* __restrict__ b34) {
    int i = blockIdx.x * blockDim.x + threadIdx.x;    // < 5120
    if (i < 3 * DD) b12[i] = qkv_b[i];
    else            b12[i] = fc1_b[i - 3 * DD];
    if (i < DD)     b34[i] = out_b[i] + fc2_b[i];
}

__global__ void expw_k(const float* __restrict__ pb, __half* __restrict__ w, int n) {
    int i = blockIdx.x * blockDim.x + threadIdx.x;
    if (i < n) w[i] = __float2half_rn(expf(pb[i]));
}

// LayerNorm over last dim (D=1024); one block (256 thr, float4) per row.
__global__ void ln_k(const float* __restrict__ x, __half* __restrict__ h) {
    __shared__ float red[16];
    const size_t row = blockIdx.x;
    const float4* xr = (const float4*)(x + row * DD);
    float4 v = xr[threadIdx.x];
    float s = v.x + v.y + v.z + v.w;
    float q = v.x*v.x + v.y*v.y + v.z*v.z + v.w*v.w;
    #pragma unroll
    for (int o = 16; o; o >>= 1) {
        s += __shfl_xor_sync(0xffffffffu, s, o);
        q += __shfl_xor_sync(0xffffffffu, q, o);
    }
    int wid = threadIdx.x >> 5;
    if ((threadIdx.x & 31) == 0) { red[wid] = s; red[8 + wid] = q; }
    __syncthreads();
    s = 0.f; q = 0.f;
    #pragma unroll
    for (int i = 0; i < 8; i++) { s += red[i]; q += red[8 + i]; }
    float mean = s * (1.0f / DD);
    float var  = fmaxf(q * (1.0f / DD) - mean * mean, 0.0f);
    float rs   = rsqrtf(var + 1.17549435e-38f);
    __half2* hr = (__half2*)(h + row * DD);
    hr[2*threadIdx.x]     = __floats2half2_rn((v.x - mean) * rs, (v.y - mean) * rs);
    hr[2*threadIdx.x + 1] = __floats2half2_rn((v.z - mean) * rs, (v.w - mean) * rs);
}

// Build XT interleaved: row 2n = ek*v, row 2n+1 = ek, n = b*D+d, col j = time.
__global__ void make_xt_k(const __half* __restrict__ qx, __half* __restrict__ XT) {
    __shared__ float s_ekv[32][33];
    __shared__ float s_ek [32][33];
    const int d0 = blockIdx.x * 32;
    const int j0 = blockIdx.y * 32;
    const int b  = blockIdx.z;
    const int x  = threadIdx.x;
    #pragma unroll
    for (int i = 0; i < 4; i++) {
        int j = threadIdx.y + i * 8;
        const __half* row = qx + ((size_t)(j0 + j) * BB + b) * (5 * DD);
        float kk = __half2float(row[DD + d0 + x]);
        float vv = __half2float(row[2 * DD + d0 + x]);
        float ek = expf(kk);
        s_ek[j][x]  = ek;
        s_ekv[j][x] = ek * vv;
    }
    __syncthreads();
    #pragma unroll
    for (int i = 0; i < 4; i++) {
        int d = threadIdx.y + i * 8;
        size_t n = (size_t)b * DD + d0 + d;
        XT[(2 * n) * TT + j0 + x]     = __float2half_rn(s_ekv[x][d]);
        XT[(2 * n + 1) * TT + j0 + x] = __float2half_rn(s_ek[x][d]);
    }
}

// ag[:, 1024:2048] = fp16( x1 * mish(gate) ), mish(x) = x*tanh(softplus(x))
__global__ void swiglu_k(const __half* __restrict__ qx, __half* __restrict__ ag) {
    size_t idx = (size_t)blockIdx.x * blockDim.x + threadIdx.x;
    int m = (int)(idx >> 10);
    int d = (int)(idx & 1023);
    const __half* r = qx + (size_t)m * (5 * DD);
    float x1 = __half2float(r[3 * DD + d]);
    float gt = __half2float(r[4 * DD + d]);
    float sp = (gt > 20.0f) ? gt : log1pf(expf(gt));
    ag[(size_t)m * (2 * DD) + DD + d] = __float2half_rn(x1 * gt * tanhf(sp));
}

// ---------------------------------------------------------------------------
// GEMM common tile config
// fp16 mma.sync m16n8k16 (fp32 accum), 128x128x32 block tile, 8 warps,
// cp.async 4-stage smem pipeline, ldmatrix.x4 fragment loads,
// 40-half row padding (conflict-free for both cp.async stores and LDSM).
// ---------------------------------------------------------------------------
#define BM 128
#define BN 128
#define BK 32                                   // halves per k-tile
#define STRH 40                                 // halves per smem row (pad 32->40)
#define STAGES 4
#define TILE_H (BM * STRH)                      // halves per matrix per stage (5120)
#define STAGE_H (2 * TILE_H)                    // A + B per stage
#define SMEM_BYTES (STAGES * STAGE_H * 2)       // 81,920 B

// Shared mainloop body as a macro-free pattern: implemented twice (generic + aft).

template<typename OutT, bool HAS_BIAS, bool HAS_AUX>
__global__ void __launch_bounds__(256) gemm_tn(
    const __half* __restrict__ A, const __half* __restrict__ B,
    const float* __restrict__ bias, const float* __restrict__ aux,
    OutT* __restrict__ C, int M, int N, int K)
{
    extern __shared__ __half sm[];
    const uint32_t smBase = (uint32_t)__cvta_generic_to_shared(sm);

    const int tid = threadIdx.x;
    const size_t m0 = (size_t)blockIdx.y * BM;
    const size_t n0 = (size_t)blockIdx.x * BN;

    // global->smem: per matrix 128 rows x 4 chunks(16B), 2 chunks per thread
    const int lr = tid >> 2;
    const int lc = tid & 3;
    const __half* gA = A + (m0 + lr) * (size_t)K + lc * 8;
    const __half* gB = B + (n0 + lr) * (size_t)K + lc * 8;
    const uint32_t sAa = smBase + (lr * STRH + lc * 8) * 2;
    const uint32_t sBa = sAa + TILE_H * 2;

    const int warp = tid >> 5, lane = tid & 31;
    const int g = lane >> 2, tg = lane & 3;
    const int wm = (warp >> 2) * 64;
    const int wn = (warp & 3) * 32;

    // ldmatrix per-lane byte offsets within a stage tile
    uint32_t aOff[4], bOff[2];
    {
        const int arow = lane & 15, akoff = (lane >> 4) * 8;
        #pragma unroll
        for (int mt = 0; mt < 4; mt++)
            aOff[mt] = ((wm + mt * 16 + arow) * STRH + akoff) * 2;
        const int brow = 8 * (lane >> 4) + (lane & 7);
        const int bkoff = ((lane >> 3) & 1) * 8;
        #pragma unroll
        for (int p = 0; p < 2; p++)
            bOff[p] = ((wn + 16 * p + brow) * STRH + bkoff) * 2;
    }

    float c[4][4][4];
    #pragma unroll
    for (int i = 0; i < 4; i++)
        #pragma unroll
        for (int j = 0; j < 4; j++)
            #pragma unroll
            for (int e = 0; e < 4; e++) c[i][j][e] = 0.0f;

    const int nk = K / BK;

    #pragma unroll
    for (int st = 0; st < STAGES - 1; st++) {
        const uint32_t da = sAa + st * STAGE_H * 2;
        const uint32_t db = sBa + st * STAGE_H * 2;
        const size_t ko = (size_t)st * BK;
        #pragma unroll
        for (int i = 0; i < 2; i++) {
            cp_async16(da + i * 64 * STRH * 2, gA + ko + (size_t)(64 * i) * K);
            cp_async16(db + i * 64 * STRH * 2, gB + ko + (size_t)(64 * i) * K);
        }
        cp_commit();
    }

    int slot = 0, wslot = STAGES - 1;
    for (int kt = 0; kt < nk; kt++) {
        asm volatile("cp.async.wait_group %0;\n" :: "n"(STAGES - 2) : "memory");
        __syncthreads();

        if (kt + STAGES - 1 < nk) {
            const uint32_t da = sAa + wslot * STAGE_H * 2;
            const uint32_t db = sBa + wslot * STAGE_H * 2;
            const size_t ko = (size_t)(kt + STAGES - 1) * BK;
            #pragma unroll
            for (int i = 0; i < 2; i++) {
                cp_async16(da + i * 64 * STRH * 2, gA + ko + (size_t)(64 * i) * K);
                cp_async16(db + i * 64 * STRH * 2, gB + ko + (size_t)(64 * i) * K);
            }
        }
        cp_commit();

        const uint32_t aTile = smBase + slot * STAGE_H * 2;
        const uint32_t bTile = aTile + TILE_H * 2;
        #pragma unroll
        for (int ks = 0; ks < 2; ks++) {
            const uint32_t kb = ks * 32;          // 16 halves
            uint32_t af[4][4], bf[4][2];
            #pragma unroll
            for (int mt = 0; mt < 4; mt++)
                ldsm_x4(af[mt][0], af[mt][1], af[mt][2], af[mt][3], aTile + aOff[mt] + kb);
            #pragma unroll
            for (int p = 0; p < 2; p++)
                ldsm_x4(bf[2*p][0], bf[2*p][1], bf[2*p+1][0], bf[2*p+1][1],
                        bTile + bOff[p] + kb);
            #pragma unroll
            for (int mt = 0; mt < 4; mt++)
                #pragma unroll
                for (int nt = 0; nt < 4; nt++) {
                    asm volatile(
                        "mma.sync.aligned.m16n8k16.row.col.f32.f16.f16.f32 "
                        "{%0,%1,%2,%3}, {%4,%5,%6,%7}, {%8,%9}, {%0,%1,%2,%3};\n"
                        : "+f"(c[mt][nt][0]), "+f"(c[mt][nt][1]),
                          "+f"(c[mt][nt][2]), "+f"(c[mt][nt][3])
                        : "r"(af[mt][0]), "r"(af[mt][1]), "r"(af[mt][2]), "r"(af[mt][3]),
                          "r"(bf[nt][0]), "r"(bf[nt][1]));
                }
        }
        slot  = (slot  == STAGES - 1) ? 0 : slot + 1;
        wslot = (wslot == STAGES - 1) ? 0 : wslot + 1;
    }

    // epilogue
    #pragma unroll
    for (int mt = 0; mt < 4; mt++) {
        const size_t r0 = m0 + wm + mt * 16 + g;
        const size_t r1 = r0 + 8;
        #pragma unroll
        for (int nt = 0; nt < 4; nt++) {
            const size_t col = n0 + wn + nt * 8 + tg * 2;
            float b0 = 0.f, b1 = 0.f;
            if (HAS_BIAS) { b0 = bias[col]; b1 = bias[col + 1]; }
            const size_t i0 = r0 * N + col;
            const size_t i1 = r1 * N + col;
            float v0 = c[mt][nt][0] + b0;
            float v1 = c[mt][nt][1] + b1;
            float v2 = c[mt][nt][2] + b0;
            float v3 = c[mt][nt][3] + b1;
            if (HAS_AUX) {
                v0 += aux[i0]; v1 += aux[i0 + 1];
                v2 += aux[i1]; v3 += aux[i1 + 1];
            }
            if constexpr (sizeof(OutT) == 2) {
                *(__half2*)((__half*)C + i0) = __floats2half2_rn(v0, v1);
                *(__half2*)((__half*)C + i1) = __floats2half2_rn(v2, v3);
            } else {
                ((float*)C)[i0] = v0; ((float*)C)[i0 + 1] = v1;
                ((float*)C)[i1] = v2; ((float*)C)[i1 + 1] = v3;
            }
        }
    }
}

// Y-GEMM with fused AFT activation epilogue.
// A = W [T,T], B = XT [16384, T] (row 2n = ekv, 2n+1 = ek).
// accum pairs (even,odd cols) = (num, den); writes ag[:,0:1024] = sig(q)*num/den.
__global__ void __launch_bounds__(256) gemm_aft(
    const __half* __restrict__ A, const __half* __restrict__ B,
    const __half* __restrict__ qx, __half* __restrict__ ag, int N, int K)
{
    extern __shared__ __half sm[];
    const uint32_t smBase = (uint32_t)__cvta_generic_to_shared(sm);

    const int tid = threadIdx.x;
    const size_t m0 = (size_t)blockIdx.y * BM;
    const size_t n0 = (size_t)blockIdx.x * BN;

    const int lr = tid >> 2;
    const int lc = tid & 3;
    const __half* gA = A + (m0 + lr) * (size_t)K + lc * 8;
    const __half* gB = B + (n0 + lr) * (size_t)K + lc * 8;
    const uint32_t sAa = smBase + (lr * STRH + lc * 8) * 2;
    const uint32_t sBa = sAa + TILE_H * 2;

    const int warp = tid >> 5, lane = tid & 31;
    const int g = lane >> 2, tg = lane & 3;
    const int wm = (warp >> 2) * 64;
    const int wn = (warp & 3) * 32;

    uint32_t aOff[4], bOff[2];
    {
        const int arow = lane & 15, akoff = (lane >> 4) * 8;
        #pragma unroll
        for (int mt = 0; mt < 4; mt++)
            aOff[mt] = ((wm + mt * 16 + arow) * STRH + akoff) * 2;
        const int brow = 8 * (lane >> 4) + (lane & 7);
        const int bkoff = ((lane >> 3) & 1) * 8;
        #pragma unroll
        for (int p = 0; p < 2; p++)
            bOff[p] = ((wn + 16 * p + brow) * STRH + bkoff) * 2;
    }

    float c[4][4][4];
    #pragma unroll
    for (int i = 0; i < 4; i++)
        #pragma unroll
        for (int j = 0; j < 4; j++)
            #pragma unroll
            for (int e = 0; e < 4; e++) c[i][j][e] = 0.0f;

    const int nk = K / BK;

    #pragma unroll
    for (int st = 0; st < STAGES - 1; st++) {
        const uint32_t da = sAa + st * STAGE_H * 2;
        const uint32_t db = sBa + st * STAGE_H * 2;
        const size_t ko = (size_t)st * BK;
        #pragma unroll
        for (int i = 0; i < 2; i++) {
            cp_async16(da + i * 64 * STRH * 2, gA + ko + (size_t)(64 * i) * K);
            cp_async16(db + i * 64 * STRH * 2, gB + ko + (size_t)(64 * i) * K);
        }
        cp_commit();
    }

    int slot = 0, wslot = STAGES - 1;
    for (int kt = 0; kt < nk; kt++) {
        asm volatile("cp.async.wait_group %0;\n" :: "n"(STAGES - 2) : "memory");
        __syncthreads();

        if (kt + STAGES - 1 < nk) {
            const uint32_t da = sAa + wslot * STAGE_H * 2;
            const uint32_t db = sBa + wslot * STAGE_H * 2;
            const size_t ko = (size_t)(kt + STAGES - 1) * BK;
            #pragma unroll
            for (int i = 0; i < 2; i++) {
                cp_async16(da + i * 64 * STRH * 2, gA + ko + (size_t)(64 * i) * K);
                cp_async16(db + i * 64 * STRH * 2, gB + ko + (size_t)(64 * i) * K);
            }
        }
        cp_commit();

        const uint32_t aTile = smBase + slot * STAGE_H * 2;
        const uint32_t bTile = aTile + TILE_H * 2;
        #pragma unroll
        for (int ks = 0; ks < 2; ks++) {
            const uint32_t kb = ks * 32;
            uint32_t af[4][4], bf[4][2];
            #pragma unroll
            for (int mt = 0; mt < 4; mt++)
                ldsm_x4(af[mt][0], af[mt][1], af[mt][2], af[mt][3], aTile + aOff[mt] + kb);
            #pragma unroll
            for (int p = 0; p < 2; p++)
                ldsm_x4(bf[2*p][0], bf[2*p][1], bf[2*p+1][0], bf[2*p+1][1],
                        bTile + bOff[p] + kb);
            #pragma unroll
            for (int mt = 0; mt < 4; mt++)
                #pragma unroll
                for (int nt = 0; nt < 4; nt++) {
                    asm volatile(
                        "mma.sync.aligned.m16n8k16.row.col.f32.f16.f16.f32 "
                        "{%0,%1,%2,%3}, {%4,%5,%6,%7}, {%8,%9}, {%0,%1,%2,%3};\n"
                        : "+f"(c[mt][nt][0]), "+f"(c[mt][nt][1]),
                          "+f"(c[mt][nt][2]), "+f"(c[mt][nt][3])
                        : "r"(af[mt][0]), "r"(af[mt][1]), "r"(af[mt][2]), "r"(af[mt][3]),
                          "r"(bf[nt][0]), "r"(bf[nt][1]));
                }
        }
        slot  = (slot  == STAGES - 1) ? 0 : slot + 1;
        wslot = (wslot == STAGES - 1) ? 0 : wslot + 1;
    }

    // fused AFT epilogue: c[..][0]/c[..][1] = (num, den) for rows r0; [2]/[3] for r0+8
    #pragma unroll
    for (int mt = 0; mt < 4; mt++) {
        const size_t t0 = m0 + wm + mt * 16 + g;    // time index
        const size_t t1 = t0 + 8;
        #pragma unroll
        for (int nt = 0; nt < 4; nt++) {
            const int colpair = (int)((n0 + wn + nt * 8) >> 1) + tg;  // = b*1024 + d
            const int b = colpair >> 10, d = colpair & 1023;
            const size_t mrow0 = t0 * BB + b;
            const size_t mrow1 = t1 * BB + b;
            float q0 = __half2float(qx[mrow0 * (5 * DD) + d]);
            float q1 = __half2float(qx[mrow1 * (5 * DD) + d]);
            float s0 = 1.0f / (1.0f + expf(-q0));
            float s1 = 1.0f / (1.0f + expf(-q1));
            ag[mrow0 * (2 * DD) + d] =
                __float2half_rn(s0 * (c[mt][nt][0] / c[mt][nt][1]));
            ag[mrow1 * (2 * DD) + d] =
                __float2half_rn(s1 * (c[mt][nt][2] / c[mt][nt][3]));
        }
    }
}

// ---------------------------------------------------------------------------
// Host launch
// ---------------------------------------------------------------------------
extern "C" void kernel_launch(void* const* d_in, const int* in_sizes, int n_in,
                              void* d_out, int out_size) {
    const float* data  = (const float*)d_in[0];
    const float* qkv_w = (const float*)d_in[1];
    const float* qkv_b = (const float*)d_in[2];
    const float* pos_b = (const float*)d_in[3];
    const float* out_w = (const float*)d_in[4];
    const float* out_b = (const float*)d_in[5];
    const float* fc1_w = (const float*)d_in[6];
    const float* fc1_b = (const float*)d_in[7];
    const float* fc2_w = (const float*)d_in[8];
    const float* fc2_b = (const float*)d_in[9];
    float* out = (float*)d_out;

    __half *h, *qx, *W, *XT, *ag, *w12, *w34;
    float *b12, *b34;
    cudaGetSymbolAddress((void**)&h,   g_h);
    cudaGetSymbolAddress((void**)&qx,  g_qx);
    cudaGetSymbolAddress((void**)&W,   g_W);
    cudaGetSymbolAddress((void**)&XT,  g_XT);
    cudaGetSymbolAddress((void**)&ag,  g_ag);
    cudaGetSymbolAddress((void**)&w12, g_w12);
    cudaGetSymbolAddress((void**)&w34, g_w34);
    cudaGetSymbolAddress((void**)&b12, g_b12);
    cudaGetSymbolAddress((void**)&b34, g_b34);

    cudaFuncSetAttribute(gemm_tn<__half, true, false>, cudaFuncAttributeMaxDynamicSharedMemorySize, SMEM_BYTES);
    cudaFuncSetAttribute(gemm_tn<float,  true, true >, cudaFuncAttributeMaxDynamicSharedMemorySize, SMEM_BYTES);
    cudaFuncSetAttribute(gemm_aft, cudaFuncAttributeMaxDynamicSharedMemorySize, SMEM_BYTES);

    // weight / bias prep
    conv_half_k<<<(3*DD*DD + 255)/256, 256>>>(qkv_w, w12, 3*DD*DD);
    conv_half_k<<<(2*DD*DD + 255)/256, 256>>>(fc1_w, w12 + (size_t)3*DD*DD, 2*DD*DD);
    prep_w34_k<<<(DD*DD + 255)/256, 256>>>(out_w, fc2_w, w34);
    prep_bias_k<<<(5*DD + 255)/256, 256>>>(qkv_b, fc1_b, out_b, fc2_b, b12, b34);

    // layernorm + exp(pos_bias)
    ln_k<<<MROWS, 256>>>(data, h);
    expw_k<<<(TT*TT + 255)/256, 256>>>(pos_b, W, TT*TT);

    // qx = h @ w12^T + b12    [16384, 5120] fp16  (fused qkv + fc1)
    gemm_tn<__half, true, false><<<dim3(5*DD/BN, MROWS/BM), 256, SMEM_BYTES>>>(
        h, w12, b12, nullptr, qx, MROWS, 5*DD, DD);

    // gate half of ag
    swiglu_k<<<(MROWS*DD)/256, 256>>>(qx, ag);

    // XT interleaved [16384, 2048]
    make_xt_k<<<dim3(DD/32, TT/32, BB), dim3(32, 8)>>>(qx, XT);

    // act half of ag: fused W@XT^T + sigmoid(q)*num/den
    gemm_aft<<<dim3(2*BB*DD/BN, TT/BM), 256, SMEM_BYTES>>>(
        W, XT, qx, ag, 2*BB*DD, TT);

    // out = data + ag @ w34^T + b34   (fused out-proj + fc2)
    gemm_tn<float, true, true><<<dim3(DD/BN, MROWS/BM), 256, SMEM_BYTES>>>(
        ag, w34, b34, data, out, MROWS, DD, 2*DD);
}

// round 11
// speedup vs baseline: 1.9013x; 1.0525x over previous
#include <cuda_runtime.h>
#include <cuda_fp16.h>
#include <cstdint>
#include <cstdio>

// Problem dims (fixed): T=2048, B=8, D=1024
#define TT 2048
#define BB 8
#define DD 1024
#define MROWS (TT*BB)          // 16384

// ---------------------------------------------------------------------------
// Scratch (device globals; no allocation allowed)
// ---------------------------------------------------------------------------
__device__ __half g_h  [(size_t)MROWS * DD];          // layernorm(data), fp16
__device__ __half g_qx [(size_t)MROWS * 3 * DD];      // [q|k|v], fp16
__device__ __half g_W  [(size_t)TT * TT];             // exp(pos_bias), fp16
__device__ __half g_XT [(size_t)2 * BB * DD * TT];    // row 2n = ek*v, 2n+1 = ek (n=b*D+d)
__device__ __half g_ag [(size_t)MROWS * 2 * DD];      // [act | gate-ffn] per row (K=2048)
__device__ __half g_w12[(size_t)5*DD*DD];             // [qkv_w ; interleaved x1/gate fc1_w]
__device__ __half g_w34[(size_t)DD*2*DD];             // row n = [out_w[n] | fc2_w[n]]
__device__ float  g_b12[(size_t)5*DD];                // [qkv_b ; interleaved fc1_b]
__device__ float  g_b34[(size_t)DD];

// ---------------------------------------------------------------------------
// Helpers
// ---------------------------------------------------------------------------
__device__ __forceinline__ void cp_async16(uint32_t saddr, const void* gptr) {
    asm volatile("cp.async.cg.shared.global [%0], [%1], 16;\n" :: "r"(saddr), "l"(gptr));
}
__device__ __forceinline__ void cp_commit() {
    asm volatile("cp.async.commit_group;\n");
}
__device__ __forceinline__ void ldsm_x4(uint32_t& r0, uint32_t& r1, uint32_t& r2, uint32_t& r3,
                                        uint32_t addr) {
    asm volatile("ldmatrix.sync.aligned.m8n8.x4.shared.b16 {%0,%1,%2,%3}, [%4];"
                 : "=r"(r0), "=r"(r1), "=r"(r2), "=r"(r3) : "r"(addr));
}

// ---------------------------------------------------------------------------
// Elementwise / prep kernels
// ---------------------------------------------------------------------------
// w12 rows 0..3071 = qkv_w; rows 3072+2d = fc1_w[d], 3072+2d+1 = fc1_w[1024+d]
__global__ void prep_w12_k(const float* __restrict__ qkv_w, const float* __restrict__ fc1_w,
                           __half* __restrict__ w12) {
    int i = blockIdx.x * blockDim.x + threadIdx.x;    // < 4*DD*DD
    if (i < 3 * DD * DD) {
        w12[i] = __float2half_rn(qkv_w[i]);
    } else {
        int i2 = i - 3 * DD * DD;
        int d = i2 >> 10, c = i2 & 1023;
        size_t base = ((size_t)3 * DD + 2 * d) * DD;
        w12[base + c]      = __float2half_rn(fc1_w[(size_t)d * DD + c]);
        w12[base + DD + c] = __float2half_rn(fc1_w[(size_t)(DD + d) * DD + c]);
    }
}

__global__ void prep_w34_k(const float* __restrict__ out_w, const float* __restrict__ fc2_w,
                           __half* __restrict__ w34) {
    int i = blockIdx.x * blockDim.x + threadIdx.x;    // < 1024*1024
    int n = i >> 10, c = i & 1023;
    w34[(size_t)n * 2048 + c]        = __float2half_rn(out_w[i]);
    w34[(size_t)n * 2048 + 1024 + c] = __float2half_rn(fc2_w[i]);
}

__global__ void prep_bias_k(const float* __restrict__ qkv_b, const float* __restrict__ fc1_b,
                            const float* __restrict__ out_b, const float* __restrict__ fc2_b,
                            float* __restrict__ b12, float* __restrict__ b34) {
    int i = blockIdx.x * blockDim.x + threadIdx.x;    // < 4096
    if (i < 3 * DD) {
        b12[i] = qkv_b[i];
    } else {
        int d = i - 3 * DD;
        b12[3 * DD + 2 * d]     = fc1_b[d];
        b12[3 * DD + 2 * d + 1] = fc1_b[DD + d];
    }
    if (i < DD) b34[i] = out_b[i] + fc2_b[i];
}

__global__ void expw_k(const float* __restrict__ pb, __half* __restrict__ w, int n) {
    int i = blockIdx.x * blockDim.x + threadIdx.x;
    if (i < n) w[i] = __float2half_rn(expf(pb[i]));
}

// LayerNorm over last dim (D=1024); one block (256 thr, float4) per row.
__global__ void ln_k(const float* __restrict__ x, __half* __restrict__ h) {
    __shared__ float red[16];
    const size_t row = blockIdx.x;
    const float4* xr = (const float4*)(x + row * DD);
    float4 v = xr[threadIdx.x];
    float s = v.x + v.y + v.z + v.w;
    float q = v.x*v.x + v.y*v.y + v.z*v.z + v.w*v.w;
    #pragma unroll
    for (int o = 16; o; o >>= 1) {
        s += __shfl_xor_sync(0xffffffffu, s, o);
        q += __shfl_xor_sync(0xffffffffu, q, o);
    }
    int wid = threadIdx.x >> 5;
    if ((threadIdx.x & 31) == 0) { red[wid] = s; red[8 + wid] = q; }
    __syncthreads();
    s = 0.f; q = 0.f;
    #pragma unroll
    for (int i = 0; i < 8; i++) { s += red[i]; q += red[8 + i]; }
    float mean = s * (1.0f / DD);
    float var  = fmaxf(q * (1.0f / DD) - mean * mean, 0.0f);
    float rs   = rsqrtf(var + 1.17549435e-38f);
    __half2* hr = (__half2*)(h + row * DD);
    hr[2*threadIdx.x]     = __floats2half2_rn((v.x - mean) * rs, (v.y - mean) * rs);
    hr[2*threadIdx.x + 1] = __floats2half2_rn((v.z - mean) * rs, (v.w - mean) * rs);
}

// Build XT interleaved: row 2n = ek*v, row 2n+1 = ek, n = b*D+d, col j = time.
__global__ void make_xt_k(const __half* __restrict__ qx, __half* __restrict__ XT) {
    __shared__ float s_ekv[32][33];
    __shared__ float s_ek [32][33];
    const int d0 = blockIdx.x * 32;
    const int j0 = blockIdx.y * 32;
    const int b  = blockIdx.z;
    const int x  = threadIdx.x;
    #pragma unroll
    for (int i = 0; i < 4; i++) {
        int j = threadIdx.y + i * 8;
        const __half* row = qx + ((size_t)(j0 + j) * BB + b) * (3 * DD);
        float kk = __half2float(row[DD + d0 + x]);
        float vv = __half2float(row[2 * DD + d0 + x]);
        float ek = expf(kk);
        s_ek[j][x]  = ek;
        s_ekv[j][x] = ek * vv;
    }
    __syncthreads();
    #pragma unroll
    for (int i = 0; i < 4; i++) {
        int d = threadIdx.y + i * 8;
        size_t n = (size_t)b * DD + d0 + d;
        XT[(2 * n) * TT + j0 + x]     = __float2half_rn(s_ekv[x][d]);
        XT[(2 * n + 1) * TT + j0 + x] = __float2half_rn(s_ek[x][d]);
    }
}

// ---------------------------------------------------------------------------
// GEMM common tile config
// fp16 mma.sync m16n8k16 (fp32 accum), 128x128x32 block tile, 8 warps,
// cp.async 5-stage smem pipeline, ldmatrix.x4 fragment loads,
// 40-half row padding (conflict-free for both cp.async stores and LDSM).
// ---------------------------------------------------------------------------
#define BM 128
#define BN 128
#define BK 32                                   // halves per k-tile
#define STRH 40                                 // halves per smem row (pad 32->40)
#define STAGES 5
#define TILE_H (BM * STRH)                      // halves per matrix per stage (5120)
#define STAGE_H (2 * TILE_H)                    // A + B per stage
#define SMEM_BYTES (STAGES * STAGE_H * 2)       // 102,400 B

// Mainloop shared by all GEMMs (accumulates c[4][4][4])
#define GEMM_MAINLOOP(Aptr, Bptr, Kdim)                                              \
    const int lr = tid >> 2;                                                          \
    const int lc = tid & 3;                                                           \
    const __half* gA = (Aptr) + (m0 + lr) * (size_t)(Kdim) + lc * 8;                  \
    const __half* gB = (Bptr) + (n0 + lr) * (size_t)(Kdim) + lc * 8;                  \
    const uint32_t sAa = smBase + (lr * STRH + lc * 8) * 2;                           \
    const uint32_t sBa = sAa + TILE_H * 2;                                            \
    uint32_t aOff[4], bOff[2];                                                        \
    {                                                                                 \
        const int arow = lane & 15, akoff = (lane >> 4) * 8;                          \
        _Pragma("unroll")                                                             \
        for (int mt = 0; mt < 4; mt++)                                                \
            aOff[mt] = ((wm + mt * 16 + arow) * STRH + akoff) * 2;                    \
        const int brow = 8 * (lane >> 4) + (lane & 7);                                \
        const int bkoff = ((lane >> 3) & 1) * 8;                                      \
        _Pragma("unroll")                                                             \
        for (int p = 0; p < 2; p++)                                                   \
            bOff[p] = ((wn + 16 * p + brow) * STRH + bkoff) * 2;                      \
    }                                                                                 \
    const int nk = (Kdim) / BK;                                                       \
    _Pragma("unroll")                                                                 \
    for (int st = 0; st < STAGES - 1; st++) {                                         \
        const uint32_t da = sAa + st * STAGE_H * 2;                                   \
        const uint32_t db = sBa + st * STAGE_H * 2;                                   \
        const size_t ko = (size_t)st * BK;                                            \
        _Pragma("unroll")                                                             \
        for (int i = 0; i < 2; i++) {                                                 \
            cp_async16(da + i * 64 * STRH * 2, gA + ko + (size_t)(64 * i) * (Kdim));  \
            cp_async16(db + i * 64 * STRH * 2, gB + ko + (size_t)(64 * i) * (Kdim));  \
        }                                                                             \
        cp_commit();                                                                  \
    }                                                                                 \
    int slot = 0, wslot = STAGES - 1;                                                 \
    for (int kt = 0; kt < nk; kt++) {                                                 \
        asm volatile("cp.async.wait_group %0;\n" :: "n"(STAGES - 2) : "memory");      \
        __syncthreads();                                                              \
        if (kt + STAGES - 1 < nk) {                                                   \
            const uint32_t da = sAa + wslot * STAGE_H * 2;                            \
            const uint32_t db = sBa + wslot * STAGE_H * 2;                            \
            const size_t ko = (size_t)(kt + STAGES - 1) * BK;                         \
            _Pragma("unroll")                                                         \
            for (int i = 0; i < 2; i++) {                                             \
                cp_async16(da + i * 64 * STRH * 2,                                    \
                           gA + ko + (size_t)(64 * i) * (Kdim));                      \
                cp_async16(db + i * 64 * STRH * 2,                                    \
                           gB + ko + (size_t)(64 * i) * (Kdim));                      \
            }                                                                         \
        }                                                                             \
        cp_commit();                                                                  \
        const uint32_t aTile = smBase + slot * STAGE_H * 2;                           \
        const uint32_t bTile = aTile + TILE_H * 2;                                    \
        _Pragma("unroll")                                                             \
        for (int ks = 0; ks < 2; ks++) {                                              \
            const uint32_t kb = ks * 32;                                              \
            uint32_t af[4][4], bf[4][2];                                              \
            _Pragma("unroll")                                                         \
            for (int mt = 0; mt < 4; mt++)                                            \
                ldsm_x4(af[mt][0], af[mt][1], af[mt][2], af[mt][3],                   \
                        aTile + aOff[mt] + kb);                                       \
            _Pragma("unroll")                                                         \
            for (int p = 0; p < 2; p++)                                               \
                ldsm_x4(bf[2*p][0], bf[2*p][1], bf[2*p+1][0], bf[2*p+1][1],           \
                        bTile + bOff[p] + kb);                                        \
            _Pragma("unroll")                                                         \
            for (int mt = 0; mt < 4; mt++)                                            \
                _Pragma("unroll")                                                     \
                for (int nt = 0; nt < 4; nt++) {                                      \
                    asm volatile(                                                     \
                        "mma.sync.aligned.m16n8k16.row.col.f32.f16.f16.f32 "          \
                        "{%0,%1,%2,%3}, {%4,%5,%6,%7}, {%8,%9}, {%0,%1,%2,%3};\n"     \
                        : "+f"(c[mt][nt][0]), "+f"(c[mt][nt][1]),                     \
                          "+f"(c[mt][nt][2]), "+f"(c[mt][nt][3])                      \
                        : "r"(af[mt][0]), "r"(af[mt][1]),                             \
                          "r"(af[mt][2]), "r"(af[mt][3]),                             \
                          "r"(bf[nt][0]), "r"(bf[nt][1]));                            \
                }                                                                     \
        }                                                                             \
        slot  = (slot  == STAGES - 1) ? 0 : slot + 1;                                 \
        wslot = (wslot == STAGES - 1) ? 0 : wslot + 1;                                \
    }

// Projection GEMM: A = h [16384,1024], B = w12 [5120,1024].
// n < 3072: qx = q|k|v (+bias).  n >= 3072 (interleaved x1/gate): fused SwiGLU
// epilogue -> ag[:, 1024+d] = x1 * gate * tanh(softplus(gate)).
__global__ void __launch_bounds__(256) gemm_qkv(
    const __half* __restrict__ A, const __half* __restrict__ B,
    const float* __restrict__ bias,
    __half* __restrict__ qx, __half* __restrict__ ag)
{
    extern __shared__ __half sm[];
    const uint32_t smBase = (uint32_t)__cvta_generic_to_shared(sm);
    const int tid = threadIdx.x;
    const size_t m0 = (size_t)blockIdx.y * BM;
    const size_t n0 = (size_t)blockIdx.x * BN;
    const int warp = tid >> 5, lane = tid & 31;
    const int g = lane >> 2, tg = lane & 3;
    const int wm = (warp >> 2) * 64;
    const int wn = (warp & 3) * 32;

    float c[4][4][4];
    #pragma unroll
    for (int i = 0; i < 4; i++)
        #pragma unroll
        for (int j = 0; j < 4; j++)
            #pragma unroll
            for (int e = 0; e < 4; e++) c[i][j][e] = 0.0f;

    GEMM_MAINLOOP(A, B, DD)

    if (n0 < 3 * DD) {
        // plain epilogue -> qx
        #pragma unroll
        for (int mt = 0; mt < 4; mt++) {
            const size_t r0 = m0 + wm + mt * 16 + g;
            const size_t r1 = r0 + 8;
            #pragma unroll
            for (int nt = 0; nt < 4; nt++) {
                const size_t col = n0 + wn + nt * 8 + tg * 2;
                const float b0 = bias[col], b1 = bias[col + 1];
                *(__half2*)(qx + r0 * (3 * DD) + col) =
                    __floats2half2_rn(c[mt][nt][0] + b0, c[mt][nt][1] + b1);
                *(__half2*)(qx + r1 * (3 * DD) + col) =
                    __floats2half2_rn(c[mt][nt][2] + b0, c[mt][nt][3] + b1);
            }
        }
    } else {
        // fused SwiGLU epilogue -> ag[:, 1024 + d]
        #pragma unroll
        for (int mt = 0; mt < 4; mt++) {
            const size_t r0 = m0 + wm + mt * 16 + g;
            const size_t r1 = r0 + 8;
            #pragma unroll
            for (int nt = 0; nt < 4; nt++) {
                const size_t col = n0 + wn + nt * 8 + tg * 2;
                const float b0 = bias[col], b1 = bias[col + 1];
                const int d = (int)((col - 3 * DD) >> 1);
                float x1a = c[mt][nt][0] + b0, gta = c[mt][nt][1] + b1;
                float x1b = c[mt][nt][2] + b0, gtb = c[mt][nt][3] + b1;
                float spa = (gta > 20.0f) ? gta : log1pf(expf(gta));
                float spb = (gtb > 20.0f) ? gtb : log1pf(expf(gtb));
                ag[r0 * (2 * DD) + DD + d] = __float2half_rn(x1a * gta * tanhf(spa));
                ag[r1 * (2 * DD) + DD + d] = __float2half_rn(x1b * gtb * tanhf(spb));
            }
        }
    }
}

// Y-GEMM with fused AFT activation epilogue.
// A = W [T,T], B = XT [16384, T] (row 2n = ekv, 2n+1 = ek).
// accum pairs (even,odd cols) = (num, den); writes ag[:,0:1024] = sig(q)*num/den.
__global__ void __launch_bounds__(256) gemm_aft(
    const __half* __restrict__ A, const __half* __restrict__ B,
    const __half* __restrict__ qx, __half* __restrict__ ag)
{
    extern __shared__ __half sm[];
    const uint32_t smBase = (uint32_t)__cvta_generic_to_shared(sm);
    const int tid = threadIdx.x;
    const size_t m0 = (size_t)blockIdx.y * BM;
    const size_t n0 = (size_t)blockIdx.x * BN;
    const int warp = tid >> 5, lane = tid & 31;
    const int g = lane >> 2, tg = lane & 3;
    const int wm = (warp >> 2) * 64;
    const int wn = (warp & 3) * 32;

    float c[4][4][4];
    #pragma unroll
    for (int i = 0; i < 4; i++)
        #pragma unroll
        for (int j = 0; j < 4; j++)
            #pragma unroll
            for (int e = 0; e < 4; e++) c[i][j][e] = 0.0f;

    GEMM_MAINLOOP(A, B, TT)

    #pragma unroll
    for (int mt = 0; mt < 4; mt++) {
        const size_t t0 = m0 + wm + mt * 16 + g;    // time index
        const size_t t1 = t0 + 8;
        #pragma unroll
        for (int nt = 0; nt < 4; nt++) {
            const int colpair = (int)((n0 + wn + nt * 8) >> 1) + tg;  // = b*1024 + d
            const int b = colpair >> 10, d = colpair & 1023;
            const size_t mrow0 = t0 * BB + b;
            const size_t mrow1 = t1 * BB + b;
            float q0 = __half2float(qx[mrow0 * (3 * DD) + d]);
            float q1 = __half2float(qx[mrow1 * (3 * DD) + d]);
            float s0 = 1.0f / (1.0f + expf(-q0));
            float s1 = 1.0f / (1.0f + expf(-q1));
            ag[mrow0 * (2 * DD) + d] =
                __float2half_rn(s0 * (c[mt][nt][0] / c[mt][nt][1]));
            ag[mrow1 * (2 * DD) + d] =
                __float2half_rn(s1 * (c[mt][nt][2] / c[mt][nt][3]));
        }
    }
}

// Final GEMM: out = data + ag @ w34^T + b34
__global__ void __launch_bounds__(256) gemm_out(
    const __half* __restrict__ A, const __half* __restrict__ B,
    const float* __restrict__ bias, const float* __restrict__ aux,
    float* __restrict__ C)
{
    extern __shared__ __half sm[];
    const uint32_t smBase = (uint32_t)__cvta_generic_to_shared(sm);
    const int tid = threadIdx.x;
    const size_t m0 = (size_t)blockIdx.y * BM;
    const size_t n0 = (size_t)blockIdx.x * BN;
    const int warp = tid >> 5, lane = tid & 31;
    const int g = lane >> 2, tg = lane & 3;
    const int wm = (warp >> 2) * 64;
    const int wn = (warp & 3) * 32;
    const int N = DD;

    float c[4][4][4];
    #pragma unroll
    for (int i = 0; i < 4; i++)
        #pragma unroll
        for (int j = 0; j < 4; j++)
            #pragma unroll
            for (int e = 0; e < 4; e++) c[i][j][e] = 0.0f;

    GEMM_MAINLOOP(A, B, 2 * DD)

    #pragma unroll
    for (int mt = 0; mt < 4; mt++) {
        const size_t r0 = m0 + wm + mt * 16 + g;
        const size_t r1 = r0 + 8;
        #pragma unroll
        for (int nt = 0; nt < 4; nt++) {
            const size_t col = n0 + wn + nt * 8 + tg * 2;
            const float b0 = bias[col], b1 = bias[col + 1];
            const size_t i0 = r0 * N + col;
            const size_t i1 = r1 * N + col;
            C[i0]     = c[mt][nt][0] + b0 + aux[i0];
            C[i0 + 1] = c[mt][nt][1] + b1 + aux[i0 + 1];
            C[i1]     = c[mt][nt][2] + b0 + aux[i1];
            C[i1 + 1] = c[mt][nt][3] + b1 + aux[i1 + 1];
        }
    }
}

// ---------------------------------------------------------------------------
// Host launch
// ---------------------------------------------------------------------------
extern "C" void kernel_launch(void* const* d_in, const int* in_sizes, int n_in,
                              void* d_out, int out_size) {
    const float* data  = (const float*)d_in[0];
    const float* qkv_w = (const float*)d_in[1];
    const float* qkv_b = (const float*)d_in[2];
    const float* pos_b = (const float*)d_in[3];
    const float* out_w = (const float*)d_in[4];
    const float* out_b = (const float*)d_in[5];
    const float* fc1_w = (const float*)d_in[6];
    const float* fc1_b = (const float*)d_in[7];
    const float* fc2_w = (const float*)d_in[8];
    const float* fc2_b = (const float*)d_in[9];
    float* out = (float*)d_out;

    __half *h, *qx, *W, *XT, *ag, *w12, *w34;
    float *b12, *b34;
    cudaGetSymbolAddress((void**)&h,   g_h);
    cudaGetSymbolAddress((void**)&qx,  g_qx);
    cudaGetSymbolAddress((void**)&W,   g_W);
    cudaGetSymbolAddress((void**)&XT,  g_XT);
    cudaGetSymbolAddress((void**)&ag,  g_ag);
    cudaGetSymbolAddress((void**)&w12, g_w12);
    cudaGetSymbolAddress((void**)&w34, g_w34);
    cudaGetSymbolAddress((void**)&b12, g_b12);
    cudaGetSymbolAddress((void**)&b34, g_b34);

    cudaFuncSetAttribute(gemm_qkv, cudaFuncAttributeMaxDynamicSharedMemorySize, SMEM_BYTES);
    cudaFuncSetAttribute(gemm_aft, cudaFuncAttributeMaxDynamicSharedMemorySize, SMEM_BYTES);
    cudaFuncSetAttribute(gemm_out, cudaFuncAttributeMaxDynamicSharedMemorySize, SMEM_BYTES);

    // weight / bias prep
    prep_w12_k<<<(4*DD*DD + 255)/256, 256>>>(qkv_w, fc1_w, w12);
    prep_w34_k<<<(DD*DD + 255)/256, 256>>>(out_w, fc2_w, w34);
    prep_bias_k<<<(4*DD + 255)/256, 256>>>(qkv_b, fc1_b, out_b, fc2_b, b12, b34);

    // layernorm + exp(pos_bias)
    ln_k<<<MROWS, 256>>>(data, h);
    expw_k<<<(TT*TT + 255)/256, 256>>>(pos_b, W, TT*TT);

    // projection GEMM: qx = q|k|v (+bias); fused SwiGLU -> ag[:,1024:2048]
    gemm_qkv<<<dim3(5*DD/BN, MROWS/BM), 256, SMEM_BYTES>>>(h, w12, b12, qx, ag);

    // XT interleaved [16384, 2048]
    make_xt_k<<<dim3(DD/32, TT/32, BB), dim3(32, 8)>>>(qx, XT);

    // act half of ag: fused W@XT^T + sigmoid(q)*num/den
    gemm_aft<<<dim3(2*BB*DD/BN, TT/BM), 256, SMEM_BYTES>>>(W, XT, qx, ag);

    // out = data + ag @ w34^T + b34   (fused out-proj + fc2)
    gemm_out<<<dim3(DD/BN, MROWS/BM), 256, SMEM_BYTES>>>(ag, w34, b34, data, out);
}